// round 1
// baseline (speedup 1.0000x reference)
#include <cuda_runtime.h>

// Problem constants (match reference_code)
#define N_USERS 200000
#define N_ITEMS 100000
#define N_NODES (N_USERS + N_ITEMS)   // 300000
#define N_EDGES 4800000
#define EMB 64
#define BATCH 4096
#define NSEL (2 * BATCH)              // 8192 selected output rows
#define BITWORDS ((N_NODES + 31) / 32) // 9375 words = 37.5KB

// Scratch (allocation-free: __device__ globals)
__device__ int      g_slot[N_NODES];        // node -> representative output slot (valid only where bitmap set this call)
__device__ unsigned g_bitmap[BITWORDS];     // selected-node membership, rebuilt every call
__device__ float    g_acc[NSEL * EMB];      // per-slot segment-sum accumulator (2MB, L2-resident)

// ---------------------------------------------------------------------------
// Kernel 1: zero accumulator + bitmap (must happen every call; graph replays)
// ---------------------------------------------------------------------------
__global__ void k_init() {
    int i = blockIdx.x * blockDim.x + threadIdx.x;
    int stride = gridDim.x * blockDim.x;
    for (int t = i; t < NSEL * EMB; t += stride) g_acc[t] = 0.0f;
    for (int t = i; t < BITWORDS; t += stride)   g_bitmap[t] = 0u;
}

// ---------------------------------------------------------------------------
// Kernel 2: build node->slot map + membership bitmap for the 8192 selected ids
// Duplicate ids: plain-write race picks ONE representative per call (kernel
// boundary makes it consistent for the whole call); output is identical for
// any winner since acc[rep] holds the full segment sum for that node.
// ---------------------------------------------------------------------------
__global__ void k_build(const int* __restrict__ user_id,
                        const int* __restrict__ item_id) {
    int i = blockIdx.x * blockDim.x + threadIdx.x;
    if (i >= NSEL) return;
    int node = (i < BATCH) ? user_id[i] : (N_USERS + item_id[i - BATCH]);
    g_slot[node] = i;
    atomicOr(&g_bitmap[node >> 5], 1u << (node & 31));
}

// ---------------------------------------------------------------------------
// Kernel 3: filtered SpMM. Stream adj_row, bitmap-test in SMEM, and for hits
// the whole warp cooperatively gathers x0[col] (float2/lane, coalesced 256B)
// and atomicAdds into acc[slot] (coalesced, L2-resident).
// ---------------------------------------------------------------------------
__global__ void __launch_bounds__(256)
k_edges(const int* __restrict__ adj_row,
        const int* __restrict__ adj_col,
        const float* __restrict__ adj_vals,
        const float* __restrict__ user_emb,
        const float* __restrict__ item_emb) {
    __shared__ unsigned sbm[BITWORDS];
    for (int t = threadIdx.x; t < BITWORDS; t += blockDim.x)
        sbm[t] = g_bitmap[t];
    __syncthreads();

    const int lane   = threadIdx.x & 31;
    const int gwarp  = (blockIdx.x * blockDim.x + threadIdx.x) >> 5;
    const int nwarps = (gridDim.x * blockDim.x) >> 5;

    for (int base = gwarp * 32; base < N_EDGES; base += nwarps * 32) {
        int e = base + lane;
        bool act = (e < N_EDGES);
        int r = act ? adj_row[e] : 0;
        bool hit = act && ((sbm[r >> 5] >> (r & 31)) & 1u);
        unsigned m = __ballot_sync(0xffffffffu, hit);

        int c = 0, s = 0; float v = 0.0f;
        if (hit) {
            c = adj_col[e];
            v = adj_vals[e];
            s = g_slot[r];
        }
        while (m) {
            int src = __ffs(m) - 1; m &= m - 1;
            int   cc = __shfl_sync(0xffffffffu, c, src);
            float vv = __shfl_sync(0xffffffffu, v, src);
            int   ss = __shfl_sync(0xffffffffu, s, src);
            const float2* xp = (cc < N_USERS)
                ? (const float2*)(user_emb + (size_t)cc * EMB)
                : (const float2*)(item_emb + (size_t)(cc - N_USERS) * EMB);
            float2 x = xp[lane];                 // lane covers elems {2*lane, 2*lane+1}
            float* a = g_acc + (size_t)ss * EMB + 2 * lane;
            atomicAdd(a,     vv * x.x);
            atomicAdd(a + 1, vv * x.y);
        }
    }
}

// ---------------------------------------------------------------------------
// Kernel 4: out[i][j] = 2*x0[node_i][j] + acc[slot(node_i)][j]
// Output layout: rows 0..4095 = users (user_id order), 4096..8191 = items.
// ---------------------------------------------------------------------------
__global__ void k_out(const float* __restrict__ user_emb,
                      const float* __restrict__ item_emb,
                      const int* __restrict__ user_id,
                      const int* __restrict__ item_id,
                      float* __restrict__ out) {
    int idx = blockIdx.x * blockDim.x + threadIdx.x;
    if (idx >= NSEL * EMB) return;
    int i = idx >> 6;       // output row
    int j = idx & 63;       // emb dim
    int node; const float* x;
    if (i < BATCH) {
        int u = user_id[i];
        node = u;
        x = user_emb + (size_t)u * EMB;
    } else {
        int it = item_id[i - BATCH];
        node = N_USERS + it;
        x = item_emb + (size_t)it * EMB;
    }
    int rep = g_slot[node];  // representative slot (freshly written this call)
    out[idx] = 2.0f * x[j] + g_acc[(size_t)rep * EMB + j];
}

// ---------------------------------------------------------------------------
// Input order per metadata: user_emb, item_emb, adj_row, adj_col, adj_vals,
//                           user_id, item_id. Output: 2*4096*64 float32.
// ---------------------------------------------------------------------------
extern "C" void kernel_launch(void* const* d_in, const int* in_sizes, int n_in,
                              void* d_out, int out_size) {
    const float* user_emb = (const float*)d_in[0];
    const float* item_emb = (const float*)d_in[1];
    const int*   adj_row  = (const int*)d_in[2];
    const int*   adj_col  = (const int*)d_in[3];
    const float* adj_vals = (const float*)d_in[4];
    const int*   user_id  = (const int*)d_in[5];
    const int*   item_id  = (const int*)d_in[6];
    float*       out      = (float*)d_out;

    k_init<<<1024, 256>>>();
    k_build<<<(NSEL + 255) / 256, 256>>>(user_id, item_id);
    k_edges<<<444, 256>>>(adj_row, adj_col, adj_vals, user_emb, item_emb);
    k_out<<<(NSEL * EMB + 255) / 256, 256>>>(user_emb, item_emb, user_id, item_id, out);
}

// round 2
// speedup vs baseline: 1.2511x; 1.2511x over previous
#include <cuda_runtime.h>

// Problem constants (match reference_code)
#define N_USERS 200000
#define N_ITEMS 100000
#define N_NODES (N_USERS + N_ITEMS)    // 300000
#define N_EDGES 4800000                // % 128 == 0
#define EMB 64
#define BATCH 4096
#define NSEL (2 * BATCH)               // 8192 selected output rows
#define BITWORDS ((N_NODES + 31) / 32) // 9375 words = 37.5KB

// Scratch (allocation-free: __device__ globals)
__device__ int      g_slot[N_NODES];     // node -> representative output slot
__device__ unsigned g_bitmap[BITWORDS];  // selected-node membership (rebuilt per call)
__device__ float4   g_acc[NSEL * 16];    // per-slot accumulator, 2MB, 16B-aligned for red.v4

// ---------------------------------------------------------------------------
// Kernel 1: zero accumulator + bitmap (graph replays -> must re-zero per call)
// ---------------------------------------------------------------------------
__global__ void k_init() {
    int i = blockIdx.x * blockDim.x + threadIdx.x;
    int stride = gridDim.x * blockDim.x;
    const float4 z = make_float4(0.f, 0.f, 0.f, 0.f);
    for (int t = i; t < NSEL * 16; t += stride) g_acc[t] = z;
    for (int t = i; t < BITWORDS; t += stride)  g_bitmap[t] = 0u;
}

// ---------------------------------------------------------------------------
// Kernel 2: node->slot map + membership bitmap for the 8192 selected ids.
// Duplicate ids: plain-write race picks ONE representative; any winner is
// correct since acc[rep] holds the full segment sum for that node.
// ---------------------------------------------------------------------------
__global__ void k_build(const int* __restrict__ user_id,
                        const int* __restrict__ item_id) {
    int i = blockIdx.x * blockDim.x + threadIdx.x;
    if (i >= NSEL) return;
    int node = (i < BATCH) ? user_id[i] : (N_USERS + item_id[i - BATCH]);
    g_slot[node] = i;
    atomicOr(&g_bitmap[node >> 5], 1u << (node & 31));
}

// ---------------------------------------------------------------------------
// Kernel 3: filtered SpMM.
//  - int4 stream of adj_row: 128 edges per warp-iteration, 4x MLP
//  - SMEM bitmap test (~2.7% hit rate)
//  - per hit-edge: 16 lanes gather float4 of x0[col] (256B coalesced) and do
//    ONE red.global.add.v4.f32 each -> 16 vector reductions instead of 64
//    scalar atomics. Two hit-edges processed concurrently per warp.
// ---------------------------------------------------------------------------
__global__ void __launch_bounds__(256)
k_edges(const int4*  __restrict__ adj_row4,
        const int*   __restrict__ adj_col,
        const float* __restrict__ adj_vals,
        const float* __restrict__ user_emb,
        const float* __restrict__ item_emb) {
    __shared__ unsigned sbm[BITWORDS];
    for (int t = threadIdx.x; t < BITWORDS; t += blockDim.x)
        sbm[t] = g_bitmap[t];
    __syncthreads();

    const int lane   = threadIdx.x & 31;
    const int gwarp  = (blockIdx.x * blockDim.x + threadIdx.x) >> 5;
    const int nwarps = (gridDim.x * blockDim.x) >> 5;
    const int nchunks = N_EDGES / 128;          // 37500, exact

    for (int chunk = gwarp; chunk < nchunks; chunk += nwarps) {
        const int base = chunk * 128;
        int4 r4 = adj_row4[chunk * 32 + lane];  // edges base+4*lane .. +3

        #pragma unroll
        for (int k = 0; k < 4; k++) {
            int r = (k == 0) ? r4.x : (k == 1) ? r4.y : (k == 2) ? r4.z : r4.w;
            bool hit = (sbm[r >> 5] >> (r & 31)) & 1u;
            int c = 0, s = 0; float v = 0.0f;
            if (hit) {
                int e = base + 4 * lane + k;
                c = adj_col[e];
                v = adj_vals[e];
                s = g_slot[r];
            }
            unsigned m = __ballot_sync(0xffffffffu, hit);
            while (m) {
                int src0 = __ffs(m) - 1; m &= m - 1;
                int src1 = m ? (__ffs(m) - 1) : -1;
                if (src1 >= 0) m &= m - 1;

                const int half = lane >> 4;      // which of the two edges
                const int l16  = lane & 15;      // float4 index within row
                int src = half ? src1 : src0;
                bool act = (src >= 0);
                int srcc = act ? src : 0;
                int   cc = __shfl_sync(0xffffffffu, c, srcc);
                float vv = __shfl_sync(0xffffffffu, v, srcc);
                int   ss = __shfl_sync(0xffffffffu, s, srcc);
                if (act) {
                    const float4* xp = (cc < N_USERS)
                        ? (const float4*)(user_emb + (size_t)cc * EMB)
                        : (const float4*)(item_emb + (size_t)(cc - N_USERS) * EMB);
                    float4 x = xp[l16];
                    float4* a = g_acc + ss * 16 + l16;   // 16B aligned
                    asm volatile(
                        "red.global.add.v4.f32 [%0], {%1, %2, %3, %4};"
                        :: "l"(a), "f"(vv * x.x), "f"(vv * x.y),
                           "f"(vv * x.z), "f"(vv * x.w)
                        : "memory");
                }
            }
        }
    }
}

// ---------------------------------------------------------------------------
// Kernel 4: out[i][:] = 2*x0[node_i][:] + acc[rep(node_i)][:], float4-wide.
// ---------------------------------------------------------------------------
__global__ void k_out(const float* __restrict__ user_emb,
                      const float* __restrict__ item_emb,
                      const int* __restrict__ user_id,
                      const int* __restrict__ item_id,
                      float4* __restrict__ out4) {
    int idx = blockIdx.x * blockDim.x + threadIdx.x;
    if (idx >= NSEL * 16) return;
    int i = idx >> 4;        // output row
    int q = idx & 15;        // float4 index within row
    int node; const float4* x4;
    if (i < BATCH) {
        int u = user_id[i];
        node = u;
        x4 = (const float4*)(user_emb + (size_t)u * EMB);
    } else {
        int it = item_id[i - BATCH];
        node = N_USERS + it;
        x4 = (const float4*)(item_emb + (size_t)it * EMB);
    }
    int rep = g_slot[node];
    float4 x = x4[q];
    float4 a = g_acc[rep * 16 + q];
    out4[idx] = make_float4(2.0f * x.x + a.x, 2.0f * x.y + a.y,
                            2.0f * x.z + a.z, 2.0f * x.w + a.w);
}

// ---------------------------------------------------------------------------
// Inputs (metadata order): user_emb, item_emb, adj_row, adj_col, adj_vals,
//                          user_id, item_id. Output: 8192x64 float32.
// ---------------------------------------------------------------------------
extern "C" void kernel_launch(void* const* d_in, const int* in_sizes, int n_in,
                              void* d_out, int out_size) {
    const float* user_emb = (const float*)d_in[0];
    const float* item_emb = (const float*)d_in[1];
    const int4*  adj_row4 = (const int4*)d_in[2];
    const int*   adj_col  = (const int*)d_in[3];
    const float* adj_vals = (const float*)d_in[4];
    const int*   user_id  = (const int*)d_in[5];
    const int*   item_id  = (const int*)d_in[6];
    float4*      out4     = (float4*)d_out;

    k_init<<<256, 256>>>();
    k_build<<<(NSEL + 255) / 256, 256>>>(user_id, item_id);
    k_edges<<<440, 256>>>(adj_row4, adj_col, adj_vals, user_emb, item_emb);
    k_out<<<(NSEL * 16 + 255) / 256, 256>>>(user_emb, item_emb, user_id, item_id, out4);
}